// round 16
// baseline (speedup 1.0000x reference)
#include <cuda_runtime.h>

// cvx_knapsack_solver: batched PGD + knapsack projection.
// Projection: warm-started DUAL-POINT secant — each iteration evaluates the
// CURRENT g at lam and lam+DLT in one fused pass; the chord slope over that
// window is a fresh same-g slope (R7/R14/R15 post-mortems: the active set
// changes ~every PGD step, so any stale slope is first-order wrong).
// Two-sided bracket from sign(f1), sign(f2); NaN/inf-safe clamps subsume the
// lam=0 feasibility branch. Norm n taken from h(lam) (R13-proven).
// Layout: 8 lanes/row, 8 items/lane, 1 row/thread (4096 warps).

#define BROWS   16384
#define NITEMS  64
#define TPR     8
#define IPT     8
#define NPAIR   4          // IPT/2 float2 pairs
#define CAPC    102.0f
#define NPGD    120
#define ETAC    0.1f
#define NIT0    6          // dual-point secant evals, cold first projection
#define HI0     2.0f       // g(HI0)=0 guaranteed: y <= ~1.6, w >= 1
#define DLT     0.0078125f // 2^-7 chord window (exact binary)

// Packed dual-fp32 FMA (Blackwell FFMA2). mov.b64 is register pairing only.
__device__ __forceinline__ float2 fma2(float2 a, float2 b, float2 c) {
    float2 r;
    asm("{\n\t"
        ".reg .b64 ra, rb, rc, rd;\n\t"
        "mov.b64 ra, {%2, %3};\n\t"
        "mov.b64 rb, {%4, %5};\n\t"
        "mov.b64 rc, {%6, %7};\n\t"
        "fma.rn.f32x2 rd, ra, rb, rc;\n\t"
        "mov.b64 {%0, %1}, rd;\n\t"
        "}"
        : "=f"(r.x), "=f"(r.y)
        : "f"(a.x), "f"(a.y), "f"(b.x), "f"(b.y), "f"(c.x), "f"(c.y));
    return r;
}

// Scalar saturating FMA: clip(a*b+c, 0, 1) in one instruction.
__device__ __forceinline__ float fmasat(float a, float b, float c) {
    float r;
    asm("fma.rn.sat.f32 %0, %1, %2, %3;" : "=f"(r) : "f"(a), "f"(b), "f"(c));
    return r;
}

// Sum over the row's 8-lane group; result valid in ALL 8 lanes.
__device__ __forceinline__ float red8(float v) {
    v += __shfl_xor_sync(0xffffffffu, v, 1);
    v += __shfl_xor_sync(0xffffffffu, v, 2);
    v += __shfl_xor_sync(0xffffffffu, v, 4);
    return v;
}

// Split-exchange reduction: half the group's lanes reduce apart, the others
// bpart; final xor-4 gives every lane both totals. 4 SHFL for two values.
__device__ __forceinline__ void red8_2(float apart, float bpart, bool hb,
                                       float& A, float& B) {
    float v = hb ? apart : bpart;
    float u = __shfl_xor_sync(0xffffffffu, v, 4);
    float t = (hb ? bpart : apart) + u;
    t += __shfl_xor_sync(0xffffffffu, t, 1);
    t += __shfl_xor_sync(0xffffffffu, t, 2);
    float o = __shfl_xor_sync(0xffffffffu, t, 4);
    A = hb ? o : t;
    B = hb ? t : o;
}

// Dual-point eval: f1 = g(lam)-CAP, f2 = g(lam+DLT)-CAP, n = ||h(lam)||^2.
// (f1,f2) share one 4-SHFL split tree; n uses an overlapping 3-SHFL tree.
__device__ __forceinline__ void eval2(const float2 x[NPAIR],
                                      const float2 w[NPAIR],
                                      float lam, bool hb,
                                      float& f1, float& f2, float& n) {
    float l1 = -lam;
    float l2 = -(lam + DLT);
    float2 s1 = make_float2(0.f, 0.f);
    float2 s2 = make_float2(0.f, 0.f);
    float2 nv = make_float2(0.f, 0.f);
#pragma unroll
    for (int j = 0; j < NPAIR; j++) {
        float2 h1, h2;
        h1.x = fmasat(l1, w[j].x, x[j].x);
        h1.y = fmasat(l1, w[j].y, x[j].y);
        h2.x = fmasat(l2, w[j].x, x[j].x);
        h2.y = fmasat(l2, w[j].y, x[j].y);
        s1 = fma2(h1, w[j], s1);
        s2 = fma2(h2, w[j], s2);
        nv = fma2(h1, h1, nv);
    }
    float F1, F2;
    red8_2(s1.x + s1.y, s2.x + s2.y, hb, F1, F2);
    n = red8(nv.x + nv.y);              // independent tree, overlaps red8_2
    f1 = F1 - CAPC;
    f2 = F2 - CAPC;
}

// One chord-secant step from the pair (f1 at lam, f2 at lam+DLT).
// g decreasing => f2 <= f1; rdc >= 0 (inf/NaN when flat -> clamps catch it).
__device__ __forceinline__ float chord_step(float lam, float f1, float f2) {
    float rdc = __fdividef(DLT, f1 - f2);
    bool over1 = f1 > 0.f;              // root > lam
    bool over2 = f2 > 0.f;              // root > lam+DLT
    float lo = over2 ? (lam + DLT) : (over1 ? lam : 0.f);
    float hi = over1 ? (over2 ? HI0 : (lam + DLT)) : lam;
    float ln = fmaf(f1, rdc, lam);
    ln = fmaxf(ln, lo);                 // NaN/inf-safe clamps
    ln = fminf(ln, hi);
    return ln;
}

// x = clip(x - lam*w, 0, 1): 8 bare saturating FMAs.
__device__ __forceinline__ void applyx(float2 x[NPAIR],
                                       const float2 w[NPAIR], float lam) {
    float nl = -lam;
#pragma unroll
    for (int j = 0; j < NPAIR; j++) {
        x[j].x = fmasat(nl, w[j].x, x[j].x);
        x[j].y = fmasat(nl, w[j].y, x[j].y);
    }
}

// Cold-path apply that also returns this lane's exact ||x||^2 partial.
__device__ __forceinline__ float applyp(float2 x[NPAIR],
                                        const float2 w[NPAIR], float lam) {
    float nl = -lam;
    float a0 = 0.f, a1 = 0.f;
#pragma unroll
    for (int j = 0; j < NPAIR; j++) {
        float hx = fmasat(nl, w[j].x, x[j].x);
        float hy = fmasat(nl, w[j].y, x[j].y);
        x[j].x = hx;
        x[j].y = hy;
        a0 = fmaf(hx, hx, a0);
        a1 = fmaf(hy, hy, a1);
    }
    return a0 + a1;
}

__global__ void __launch_bounds__(64)
cvx_knapsack_kernel(const float* __restrict__ costs,
                    const float* __restrict__ wg,
                    float* __restrict__ out) {
    int tid = blockIdx.x * blockDim.x + threadIdx.x;
    int row = tid >> 3;
    int q   = tid & 7;
    if (row >= BROWS) return;
    bool hb = (q & 4) != 0;

    float2 w[NPAIR], ec[NPAIR], x[NPAIR];

    const float4* wp = reinterpret_cast<const float4*>(wg + q * IPT);
#pragma unroll
    for (int j = 0; j < NPAIR / 2; j++) {
        float4 wv = wp[j];
        w[2*j]     = make_float2(wv.x, wv.y);
        w[2*j + 1] = make_float2(wv.z, wv.w);
    }

    const float4* cp = reinterpret_cast<const float4*>(costs + row * NITEMS + q * IPT);
#pragma unroll
    for (int j = 0; j < NPAIR / 2; j++) {
        float4 cv = cp[j];
        x[2*j].x   = __saturatef(cv.x);         // clip(c, 0, 1)
        x[2*j].y   = __saturatef(cv.y);
        x[2*j+1].x = __saturatef(cv.z);
        x[2*j+1].y = __saturatef(cv.w);
        ec[2*j]   = make_float2(ETAC * cv.x, ETAC * cv.y);
        ec[2*j+1] = make_float2(ETAC * cv.z, ETAC * cv.w);
    }

    float lam = 0.f;
    float n;        // ||x||^2 estimate (refreshed every iteration from h(lam))

    // Cold projection: NIT0 dual-point chord-secant iterations.
    {
#pragma unroll 1
        for (int it = 0; it < NIT0; it++) {
            float f1, f2, nn;
            eval2(x, w, lam, hb, f1, f2, nn);
            lam = chord_step(lam, f1, f2);
        }
        n = red8(applyp(x, w, lam));
    }

    // 120 PGD steps: x = project(k*x + eta*c), k = 1 - eta/||x||  (MU = 1).
    // Warm projection: ONE fused dual-point eval -> fresh same-g chord slope.
#pragma unroll 1
    for (int t = 0; t < NPGD; t++) {
        float inv = rsqrtf(n + 1e-12f);
        float k   = fmaf(-ETAC, inv, 1.0f);
        float2 kk = make_float2(k, k);
#pragma unroll
        for (int j = 0; j < NPAIR; j++)
            x[j] = fma2(kk, x[j], ec[j]);

        float f1, f2, nn;
        eval2(x, w, lam, hb, f1, f2, nn);
        n = nn;
        lam = chord_step(lam, f1, f2);

        applyx(x, w, lam);
    }

    float4* op = reinterpret_cast<float4*>(out + row * NITEMS + q * IPT);
#pragma unroll
    for (int j = 0; j < NPAIR / 2; j++) {
        float4 v;
        v.x = x[2*j].x;     v.y = x[2*j].y;
        v.z = x[2*j + 1].x; v.w = x[2*j + 1].y;
        op[j] = v;
    }
}

extern "C" void kernel_launch(void* const* d_in, const int* in_sizes, int n_in,
                              void* d_out, int out_size) {
    const float* costs = (const float*)d_in[0];
    const float* wts   = (const float*)d_in[1];
    if (n_in >= 2 && in_sizes[0] == NITEMS) {   // guard against input order swap
        costs = (const float*)d_in[1];
        wts   = (const float*)d_in[0];
    }
    float* out = (float*)d_out;

    const int threads = 64;
    const int total   = BROWS * TPR;                       // 131072 threads
    const int blocks  = (total + threads - 1) / threads;   // 2048 blocks
    cvx_knapsack_kernel<<<blocks, threads>>>(costs, wts, out);
}

// round 17
// speedup vs baseline: 1.6413x; 1.6413x over previous
#include <cuda_runtime.h>

// cvx_knapsack_solver: batched PGD + knapsack projection. R13 algorithm:
// warm-started single-eval Newton on piecewise-linear g — each eval returns
// f = g(lam)-CAP, the exact CURRENT-g derivative d = sum_interior w^2, and
// the norm n=||h||^2 for the next step's gradient scale (f/d via a 4-SHFL
// split tree, n via an overlapping 3-SHFL tree). R17 micro-cuts:
// rcp.approx for 1/d, global [0,2] clamp (fresh-slope Newton always steps
// toward the root), dual s-accumulators. 8 lanes/row, 1 row/thread.

#define BROWS   16384
#define NITEMS  64
#define TPR     8
#define IPT     8
#define NPAIR   4          // IPT/2 float2 pairs
#define CAPC    102.0f
#define NPGD    120
#define ETAC    0.1f
#define NIT0    6          // Newton evals, cold first projection
#define HI0     2.0f       // g(HI0)=0 guaranteed: y <= ~1.6, w >= 1

// Packed dual-fp32 FMA (Blackwell FFMA2). mov.b64 is register pairing only.
__device__ __forceinline__ float2 fma2(float2 a, float2 b, float2 c) {
    float2 r;
    asm("{\n\t"
        ".reg .b64 ra, rb, rc, rd;\n\t"
        "mov.b64 ra, {%2, %3};\n\t"
        "mov.b64 rb, {%4, %5};\n\t"
        "mov.b64 rc, {%6, %7};\n\t"
        "fma.rn.f32x2 rd, ra, rb, rc;\n\t"
        "mov.b64 {%0, %1}, rd;\n\t"
        "}"
        : "=f"(r.x), "=f"(r.y)
        : "f"(a.x), "f"(a.y), "f"(b.x), "f"(b.y), "f"(c.x), "f"(c.y));
    return r;
}

// Scalar saturating FMA: clip(a*b+c, 0, 1) in one instruction.
__device__ __forceinline__ float fmasat(float a, float b, float c) {
    float r;
    asm("fma.rn.sat.f32 %0, %1, %2, %3;" : "=f"(r) : "f"(a), "f"(b), "f"(c));
    return r;
}

// 1.0f if a==b else 0.0f (single FSET).
__device__ __forceinline__ float seteqf(float a, float b) {
    float r;
    asm("set.eq.f32.f32 %0, %1, %2;" : "=f"(r) : "f"(a), "f"(b));
    return r;
}

// Fast reciprocal: single MUFU.RCP (error < 2^-22, harmless to the Newton step).
__device__ __forceinline__ float rcpf(float a) {
    float r;
    asm("rcp.approx.f32 %0, %1;" : "=f"(r) : "f"(a));
    return r;
}

// Sum over the row's 8-lane group; result valid in ALL 8 lanes.
__device__ __forceinline__ float red8(float v) {
    v += __shfl_xor_sync(0xffffffffu, v, 1);
    v += __shfl_xor_sync(0xffffffffu, v, 2);
    v += __shfl_xor_sync(0xffffffffu, v, 4);
    return v;
}

// Split-exchange reduction: half the group's lanes reduce apart, the others
// bpart; final xor-4 gives every lane both totals. 4 SHFL for two values.
__device__ __forceinline__ void red8_2(float apart, float bpart, bool hb,
                                       float& A, float& B) {
    float v = hb ? apart : bpart;
    float u = __shfl_xor_sync(0xffffffffu, v, 4);
    float t = (hb ? bpart : apart) + u;
    t += __shfl_xor_sync(0xffffffffu, t, 1);
    t += __shfl_xor_sync(0xffffffffu, t, 2);
    float o = __shfl_xor_sync(0xffffffffu, t, 4);
    A = hb ? o : t;
    B = hb ? t : o;
}

// Fused eval: f = g(lam)-CAP, d = sum_{interior} w^2, n = ||h||^2 with
// h = clip(x - lam*w, 0, 1). Dual s-accumulators shorten the FFMA2 chain.
__device__ __forceinline__ void evalgdn(const float2 x[NPAIR],
                                        const float2 w[NPAIR],
                                        const float2 w2[NPAIR],
                                        float lam, bool hb,
                                        float& f, float& d, float& n) {
    float nl = -lam;
    float2 m  = make_float2(nl, nl);
    float2 sa = make_float2(0.f, 0.f);
    float2 sb = make_float2(0.f, 0.f);
    float2 dv = make_float2(0.f, 0.f);
    float2 nv = make_float2(0.f, 0.f);
#pragma unroll
    for (int j = 0; j < NPAIR; j++) {
        float2 z = fma2(m, w[j], x[j]);
        float2 h;
        h.x = fmasat(nl, w[j].x, x[j].x);
        h.y = fmasat(nl, w[j].y, x[j].y);
        if (j & 1) sb = fma2(h, w[j], sb);
        else       sa = fma2(h, w[j], sa);
        float2 ind;
        ind.x = seteqf(h.x, z.x);       // interior <=> unclipped
        ind.y = seteqf(h.y, z.y);
        dv = fma2(ind, w2[j], dv);
        nv = fma2(h, h, nv);
    }
    float F, D;
    red8_2(sa.x + sa.y + sb.x + sb.y, dv.x + dv.y, hb, F, D);
    n = red8(nv.x + nv.y);              // independent tree, overlaps red8_2
    f = F - CAPC;
    d = D;
}

// x = clip(x - lam*w, 0, 1): 8 bare saturating FMAs.
__device__ __forceinline__ void applyx(float2 x[NPAIR],
                                       const float2 w[NPAIR], float lam) {
    float nl = -lam;
#pragma unroll
    for (int j = 0; j < NPAIR; j++) {
        x[j].x = fmasat(nl, w[j].x, x[j].x);
        x[j].y = fmasat(nl, w[j].y, x[j].y);
    }
}

// Cold-path apply that also returns this lane's exact ||x||^2 partial.
__device__ __forceinline__ float applyp(float2 x[NPAIR],
                                        const float2 w[NPAIR], float lam) {
    float nl = -lam;
    float a0 = 0.f, a1 = 0.f;
#pragma unroll
    for (int j = 0; j < NPAIR; j++) {
        float hx = fmasat(nl, w[j].x, x[j].x);
        float hy = fmasat(nl, w[j].y, x[j].y);
        x[j].x = hx;
        x[j].y = hy;
        a0 = fmaf(hx, hx, a0);
        a1 = fmaf(hy, hy, a1);
    }
    return a0 + a1;
}

__global__ void __launch_bounds__(64)
cvx_knapsack_kernel(const float* __restrict__ costs,
                    const float* __restrict__ wg,
                    float* __restrict__ out) {
    int tid = blockIdx.x * blockDim.x + threadIdx.x;
    int row = tid >> 3;
    int q   = tid & 7;
    if (row >= BROWS) return;
    bool hb = (q & 4) != 0;

    float2 w[NPAIR], w2[NPAIR], ec[NPAIR], x[NPAIR];

    const float4* wp = reinterpret_cast<const float4*>(wg + q * IPT);
#pragma unroll
    for (int j = 0; j < NPAIR / 2; j++) {
        float4 wv = wp[j];
        w[2*j]     = make_float2(wv.x, wv.y);
        w[2*j + 1] = make_float2(wv.z, wv.w);
    }
#pragma unroll
    for (int j = 0; j < NPAIR; j++)
        w2[j] = make_float2(w[j].x * w[j].x, w[j].y * w[j].y);

    const float4* cp = reinterpret_cast<const float4*>(costs + row * NITEMS + q * IPT);
#pragma unroll
    for (int j = 0; j < NPAIR / 2; j++) {
        float4 cv = cp[j];
        x[2*j].x   = __saturatef(cv.x);         // clip(c, 0, 1)
        x[2*j].y   = __saturatef(cv.y);
        x[2*j+1].x = __saturatef(cv.z);
        x[2*j+1].y = __saturatef(cv.w);
        ec[2*j]   = make_float2(ETAC * cv.x, ETAC * cv.y);
        ec[2*j+1] = make_float2(ETAC * cv.z, ETAC * cv.w);
    }

    float lam = 0.f;
    float n;    // ||x||^2 estimate for the next gradient step

    // Cold projection: NIT0 bracketed Newton iterations (persistent bracket).
    {
        float lo = 0.f, hi = HI0;
#pragma unroll 1
        for (int it = 0; it < NIT0; it++) {
            float f, d, nn;
            evalgdn(x, w, w2, lam, hb, f, d, nn);
            bool over = f > 0.f;
            lo = over ? lam : lo;
            hi = over ? hi  : lam;
            float ln = fmaf(f, rcpf(d), lam);
            ln = fmaxf(ln, lo);                 // NaN/inf-safe clamps
            ln = fminf(ln, hi);
            lam = ln;
        }
        n = red8(applyp(x, w, lam));
    }

    // 120 PGD steps: x = project(k*x + eta*c), k = 1 - eta/||x||  (MU = 1).
    // Warm projection: ONE fused Newton eval with a fresh same-g slope; a
    // fresh-slope step always moves toward the root, so the global [0,2]
    // clamp (NaN-safe) is an equivalent safeguard to per-step brackets.
#pragma unroll 1
    for (int t = 0; t < NPGD; t++) {
        float inv = rsqrtf(n + 1e-12f);
        float k   = fmaf(-ETAC, inv, 1.0f);
        float2 kk = make_float2(k, k);
#pragma unroll
        for (int j = 0; j < NPAIR; j++)
            x[j] = fma2(kk, x[j], ec[j]);

        float f, d, nn;
        evalgdn(x, w, w2, lam, hb, f, d, nn);
        float ln = fmaf(f, rcpf(d), lam);
        ln = fmaxf(ln, 0.f);                    // NaN-safe global clamp
        ln = fminf(ln, HI0);
        lam = ln;
        n = nn;

        applyx(x, w, lam);
    }

    float4* op = reinterpret_cast<float4*>(out + row * NITEMS + q * IPT);
#pragma unroll
    for (int j = 0; j < NPAIR / 2; j++) {
        float4 v;
        v.x = x[2*j].x;     v.y = x[2*j].y;
        v.z = x[2*j + 1].x; v.w = x[2*j + 1].y;
        op[j] = v;
    }
}

extern "C" void kernel_launch(void* const* d_in, const int* in_sizes, int n_in,
                              void* d_out, int out_size) {
    const float* costs = (const float*)d_in[0];
    const float* wts   = (const float*)d_in[1];
    if (n_in >= 2 && in_sizes[0] == NITEMS) {   // guard against input order swap
        costs = (const float*)d_in[1];
        wts   = (const float*)d_in[0];
    }
    float* out = (float*)d_out;

    const int threads = 64;
    const int total   = BROWS * TPR;                       // 131072 threads
    const int blocks  = (total + threads - 1) / threads;   // 2048 blocks
    cvx_knapsack_kernel<<<blocks, threads>>>(costs, wts, out);
}